// round 1
// baseline (speedup 1.0000x reference)
#include <cuda_runtime.h>

// Problem constants
#define BB   64      // batch
#define L0   128     // input length
#define C0   16      // input channels
#define L1C  124     // len after block1
#define CH1  128     // channels after block1
#define L2C  120     // len after block2
#define CH2  1024    // channels after block2
#define L3C  116     // len after block3
#define CH3  8192    // channels after block3

// Scratch (device globals; no runtime allocation allowed)
__device__ float g_out1[BB * L1C * CH1];   // [b][l][ch1]  ~4 MB
__device__ float g_x2  [BB * L2C * CH2];   // [b][l][ch2]  ~31.5 MB
__device__ float g_acc [BB * 2];           // dense accumulators

// ---------------------------------------------------------------------------
__global__ void zero_kernel() {
    g_acc[threadIdx.x] = 0.f;
}

// ---------------------------------------------------------------------------
// Block1: y1[b,l,o] = relu(sum_k state[b,l+k,o/8] * k1[k,o] + b1[o])
// One thread per output element (1.016M).
__global__ void block1_kernel(const float* __restrict__ state,
                              const float* __restrict__ k1w,
                              const float* __restrict__ b1) {
    int idx = blockIdx.x * blockDim.x + threadIdx.x;
    if (idx >= BB * L1C * CH1) return;
    int o = idx & (CH1 - 1);
    int l = (idx >> 7) % L1C;
    int b = idx / (L1C * CH1);
    int c = o >> 3;
    const float* sp = state + (b * L0 + l) * C0 + c;
    float v = b1[o];
#pragma unroll
    for (int k = 0; k < 5; k++) v = fmaf(sp[k * C0], k1w[k * CH1 + o], v);
    g_out1[idx] = fmaxf(v, 0.f);
}

// ---------------------------------------------------------------------------
// Block2: x2[b,l,o] = relu(sum_k out1[b,l+k,o/8] * k2[k,o] + b2[o])
// Thread per (b, o), rolling window over l. 65536 threads.
__global__ void block2_kernel(const float* __restrict__ k2w,
                              const float* __restrict__ b2) {
    int idx = blockIdx.x * blockDim.x + threadIdx.x;
    int o = idx & (CH2 - 1);
    int b = idx >> 10;
    int c = o >> 3;
    float w[5];
#pragma unroll
    for (int k = 0; k < 5; k++) w[k] = k2w[k * CH2 + o];
    float bias = b2[o];
    const float* ip = g_out1 + b * L1C * CH1 + c;
    float win[5];
#pragma unroll
    for (int k = 0; k < 4; k++) win[k] = ip[k * CH1];
    float* op = g_x2 + b * L2C * CH2 + o;
    for (int l = 0; l < L2C; l++) {
        win[4] = ip[(l + 4) * CH1];
        float v = bias;
#pragma unroll
        for (int k = 0; k < 5; k++) v = fmaf(win[k], w[k], v);
        op[l * CH2] = fmaxf(v, 0.f);
#pragma unroll
        for (int k = 0; k < 4; k++) win[k] = win[k + 1];
    }
}

// ---------------------------------------------------------------------------
// Block3 fused with dense: for each (b, c in [0,1024)), rolling 5-window of
// x2(b,:,c); for each l compute the 8 filter outputs, relu, and contract with
// W rows (l*8192 + c*8 + f), cols {0,1}. 4 batches per thread for W reuse.
// Grid: x = 64 c-tiles (16 c each), y = 5 l-chunks (24 l each, last 20).
// Block: 256 threads = 16 batch-groups x 16 c.
__global__ void __launch_bounds__(256)
block3_kernel(const float* __restrict__ k3w,
              const float* __restrict__ b3,
              const float* __restrict__ W) {
    int cl = threadIdx.x & 15;
    int c  = blockIdx.x * 16 + cl;
    int bg = threadIdx.x >> 4;     // 0..15
    int b0 = bg * 4;
    int l0 = blockIdx.y * 24;
    int l1 = min(L3C, l0 + 24);

    float w[5][8];
#pragma unroll
    for (int k = 0; k < 5; k++)
#pragma unroll
        for (int f = 0; f < 8; f++) w[k][f] = k3w[k * CH3 + c * 8 + f];
    float bias[8];
#pragma unroll
    for (int f = 0; f < 8; f++) bias[f] = b3[c * 8 + f];

    float xw[4][5];
#pragma unroll
    for (int j = 0; j < 4; j++)
#pragma unroll
        for (int k = 0; k < 5; k++)
            xw[j][k] = g_x2[((b0 + j) * L2C + l0 + k) * CH2 + c];

    float acc0[4] = {0.f, 0.f, 0.f, 0.f};
    float acc1[4] = {0.f, 0.f, 0.f, 0.f};

    for (int l = l0; l < l1; l++) {
        const float4* Wp = (const float4*)(W + ((size_t)l * CH3 + c * 8) * 2);
        float4 A = Wp[0], Bv = Wp[1], Cv = Wp[2], Dv = Wp[3];
        float wf[16] = {A.x, A.y, A.z, A.w, Bv.x, Bv.y, Bv.z, Bv.w,
                        Cv.x, Cv.y, Cv.z, Cv.w, Dv.x, Dv.y, Dv.z, Dv.w};
#pragma unroll
        for (int j = 0; j < 4; j++) {
#pragma unroll
            for (int f = 0; f < 8; f++) {
                float v = bias[f];
#pragma unroll
                for (int k = 0; k < 5; k++) v = fmaf(xw[j][k], w[k][f], v);
                v = fmaxf(v, 0.f);
                acc0[j] = fmaf(v, wf[2 * f],     acc0[j]);
                acc1[j] = fmaf(v, wf[2 * f + 1], acc1[j]);
            }
        }
        if (l + 1 < l1) {
#pragma unroll
            for (int j = 0; j < 4; j++) {
#pragma unroll
                for (int k = 0; k < 4; k++) xw[j][k] = xw[j][k + 1];
                xw[j][4] = g_x2[((b0 + j) * L2C + l + 5) * CH2 + c];
            }
        }
    }

    // Reduce across the 16 c-lanes (lanes 0..15 / 16..31 are independent groups)
#pragma unroll
    for (int j = 0; j < 4; j++) {
        float v0 = acc0[j], v1 = acc1[j];
#pragma unroll
        for (int s = 8; s > 0; s >>= 1) {
            v0 += __shfl_xor_sync(0xFFFFFFFFu, v0, s);
            v1 += __shfl_xor_sync(0xFFFFFFFFu, v1, s);
        }
        if (cl == 0) {
            atomicAdd(&g_acc[(b0 + j) * 2],     v0);
            atomicAdd(&g_acc[(b0 + j) * 2 + 1], v1);
        }
    }
}

// ---------------------------------------------------------------------------
__global__ void finalize_kernel(const float* __restrict__ bd,
                                float* __restrict__ out) {
    int i = threadIdx.x;  // 128
    out[i] = tanhf(g_acc[i] + bd[i & 1]);
}

// ---------------------------------------------------------------------------
extern "C" void kernel_launch(void* const* d_in, const int* in_sizes, int n_in,
                              void* d_out, int out_size) {
    const float* state = (const float*)d_in[0];
    const float* k1w   = (const float*)d_in[1];
    const float* b1    = (const float*)d_in[2];
    const float* k2w   = (const float*)d_in[3];
    const float* b2    = (const float*)d_in[4];
    const float* k3w   = (const float*)d_in[5];
    const float* b3    = (const float*)d_in[6];
    const float* W     = (const float*)d_in[7];
    const float* bd    = (const float*)d_in[8];
    float* out = (float*)d_out;

    zero_kernel<<<1, 128>>>();
    block1_kernel<<<(BB * L1C * CH1 + 255) / 256, 256>>>(state, k1w, b1);
    block2_kernel<<<(BB * CH2) / 256, 256>>>(k2w, b2);
    block3_kernel<<<dim3(64, 5), 256>>>(k3w, b3, W);
    finalize_kernel<<<1, 128>>>(bd, out);
}

// round 2
// speedup vs baseline: 1.3906x; 1.3906x over previous
#include <cuda_runtime.h>

// Problem constants
#define BB   64      // batch
#define L0   128     // input length
#define C0   16      // input channels
#define L1C  124     // len after block1
#define CH1  128     // channels after block1
#define L2C  120     // len after block2
#define CH2  1024    // channels after block2
#define L3C  116     // len after block3
#define CH3  8192    // channels after block3

#define NSLICE 16

// Scratch (device globals; no runtime allocation allowed)
__device__ float g_out1[BB * L1C * CH1];        // [b][l][ch1]  ~4 MB
__device__ float g_acc [NSLICE][BB * 2];        // sliced dense accumulators

// ---------------------------------------------------------------------------
__global__ void zero_kernel() {
    int i = blockIdx.x * blockDim.x + threadIdx.x;
    if (i < NSLICE * BB * 2) ((float*)g_acc)[i] = 0.f;
}

// ---------------------------------------------------------------------------
// Block1: out1[b,l,o] = relu(sum_k state[b,l+k,o/8] * k1[k,o] + b1[o])
__global__ void block1_kernel(const float* __restrict__ state,
                              const float* __restrict__ k1w,
                              const float* __restrict__ b1) {
    int idx = blockIdx.x * blockDim.x + threadIdx.x;
    if (idx >= BB * L1C * CH1) return;
    int o = idx & (CH1 - 1);
    int l = (idx >> 7) % L1C;
    int b = idx / (L1C * CH1);
    int c = o >> 3;
    const float* sp = state + (b * L0 + l) * C0 + c;
    float v = b1[o];
#pragma unroll
    for (int k = 0; k < 5; k++) v = fmaf(sp[k * C0], k1w[k * CH1 + o], v);
    g_out1[idx] = fmaxf(v, 0.f);
}

// ---------------------------------------------------------------------------
// Fused block2 + block3 + dense.
// Thread = (cl in 0..15 -> channel c, fh in {0,1} -> filter half, wg in 0..7).
// Each thread handles J=2 batches, recomputes x2 from a rolling out1 window,
// does the 4-filter conv3 + ReLU, and contracts with W columns {0,1}.
// Warp (32 lanes = 16 c x 2 fh) shfl-reduces the full c-tile+filter sum.
// Grid: x = 64 c-tiles, y = 8 l-chunks (15 l), z = 4 batch-groups (16 b).
__global__ void __launch_bounds__(256, 3)
fused23_kernel(const float* __restrict__ k2w, const float* __restrict__ b2,
               const float* __restrict__ k3w, const float* __restrict__ b3,
               const float* __restrict__ W) {
    int tid = threadIdx.x;
    int cl  = tid & 15;
    int fh  = (tid >> 4) & 1;
    int wg  = tid >> 5;                 // warp id 0..7
    int ct  = blockIdx.x;               // c-tile 0..63
    int c   = ct * 16 + cl;             // 0..1023
    int c1  = c >> 3;                   // out1 channel 0..127
    int l0  = blockIdx.y * 15;
    int l1  = min(L3C, l0 + 15);
    int bb  = blockIdx.z * 16 + wg * 2; // base batch for this warp

    // Block2 weights for channel c
    float w2[5];
#pragma unroll
    for (int k = 0; k < 5; k++) w2[k] = k2w[k * CH2 + c];
    float bias2 = b2[c];

    // Block3 weights for filters fh*4 .. fh*4+3 of channel c
    float w3[5][4], bias3[4];
#pragma unroll
    for (int k = 0; k < 5; k++)
#pragma unroll
        for (int f = 0; f < 4; f++)
            w3[k][f] = k3w[k * CH3 + c * 8 + fh * 4 + f];
#pragma unroll
    for (int f = 0; f < 4; f++) bias3[f] = b3[c * 8 + fh * 4 + f];

    // Rolling windows. Invariant entering iteration l:
    //   xw[j][k] = x2(b, l+k, c)        k = 0..4
    //   ow[j][k] = out1(b, l+4+k, c1)   k = 0..4
    float ow[2][5], xw[2][5];
#pragma unroll
    for (int j = 0; j < 2; j++) {
        const float* op = g_out1 + ((size_t)(bb + j) * L1C) * CH1 + c1;
        float o[9];
#pragma unroll
        for (int k = 0; k < 9; k++) o[k] = op[(l0 + k) * CH1];
#pragma unroll
        for (int k = 0; k < 5; k++) {
            float v = bias2;
#pragma unroll
            for (int q = 0; q < 5; q++) v = fmaf(o[k + q], w2[q], v);
            xw[j][k] = fmaxf(v, 0.f);
        }
#pragma unroll
        for (int k = 0; k < 5; k++) ow[j][k] = o[4 + k];
    }

    float acc[2][2] = {{0.f, 0.f}, {0.f, 0.f}};

#pragma unroll 5
    for (int l = l0; l < l1; l++) {
        // Dense weights for (l, c, filters fh*4..+3), cols {0,1}: 8 floats
        const float4* Wp =
            (const float4*)(W + ((size_t)l * CH3 + c * 8 + fh * 4) * 2);
        float4 A = Wp[0], Bv = Wp[1];
        float wf[8] = {A.x, A.y, A.z, A.w, Bv.x, Bv.y, Bv.z, Bv.w};
#pragma unroll
        for (int j = 0; j < 2; j++) {
#pragma unroll
            for (int f = 0; f < 4; f++) {
                float v = bias3[f];
#pragma unroll
                for (int k = 0; k < 5; k++) v = fmaf(xw[j][k], w3[k][f], v);
                v = fmaxf(v, 0.f);
                acc[j][0] = fmaf(v, wf[2 * f],     acc[j][0]);
                acc[j][1] = fmaf(v, wf[2 * f + 1], acc[j][1]);
            }
        }
        if (l + 1 < l1) {
#pragma unroll
            for (int j = 0; j < 2; j++) {
                float no = g_out1[((size_t)(bb + j) * L1C + l + 9) * CH1 + c1];
#pragma unroll
                for (int k = 0; k < 4; k++) ow[j][k] = ow[j][k + 1];
                ow[j][4] = no;
                float v = bias2;
#pragma unroll
                for (int k = 0; k < 5; k++) v = fmaf(ow[j][k], w2[k], v);
#pragma unroll
                for (int k = 0; k < 4; k++) xw[j][k] = xw[j][k + 1];
                xw[j][4] = fmaxf(v, 0.f);
            }
        }
    }

    // Full-warp reduction: sums over 16 c-lanes and both filter halves.
#pragma unroll
    for (int j = 0; j < 2; j++) {
#pragma unroll
        for (int col = 0; col < 2; col++) {
            float v = acc[j][col];
#pragma unroll
            for (int s = 16; s > 0; s >>= 1)
                v += __shfl_xor_sync(0xFFFFFFFFu, v, s);
            if ((tid & 31) == 0)
                atomicAdd(&g_acc[ct & (NSLICE - 1)][(bb + j) * 2 + col], v);
        }
    }
}

// ---------------------------------------------------------------------------
__global__ void finalize_kernel(const float* __restrict__ bd,
                                float* __restrict__ out) {
    int i = threadIdx.x;  // 128
    float v = 0.f;
#pragma unroll
    for (int s = 0; s < NSLICE; s++) v += g_acc[s][i];
    out[i] = tanhf(v + bd[i & 1]);
}

// ---------------------------------------------------------------------------
extern "C" void kernel_launch(void* const* d_in, const int* in_sizes, int n_in,
                              void* d_out, int out_size) {
    const float* state = (const float*)d_in[0];
    const float* k1w   = (const float*)d_in[1];
    const float* b1    = (const float*)d_in[2];
    const float* k2w   = (const float*)d_in[3];
    const float* b2    = (const float*)d_in[4];
    const float* k3w   = (const float*)d_in[5];
    const float* b3    = (const float*)d_in[6];
    const float* W     = (const float*)d_in[7];
    const float* bd    = (const float*)d_in[8];
    float* out = (float*)d_out;

    zero_kernel<<<(NSLICE * BB * 2 + 255) / 256, 256>>>();
    block1_kernel<<<(BB * L1C * CH1 + 255) / 256, 256>>>(state, k1w, b1);
    fused23_kernel<<<dim3(64, 8, 4), 256>>>(k2w, b2, k3w, b3, W);
    finalize_kernel<<<1, 128>>>(bd, out);
}